// round 9
// baseline (speedup 1.0000x reference)
#include <cuda_runtime.h>
#include <math.h>
#include <stdint.h>

#define CONF_TH 0.25f
#define NMS_TH  0.35f
#define FULL    0xffffffffu

static constexpr int N_IMG = 64;
static constexpr int HW    = 1024;   // 32*32
static constexpr int NCH   = 85;
static constexpr int NCLS  = 80;
static constexpr int SLOTS = 32;

static constexpr int CHUNK_CH    = 5;                      // channels per chunk
static constexpr int CHUNK_BYTES = CHUNK_CH * HW * 4;      // 20480
static constexpr int NCHUNK      = NCH / CHUNK_CH;         // 17
static constexpr int RING        = 8;

// dynamic smem layout (bytes):
//  ring   float[8*5120]   @      0 (163840)
//  sbox   float4[1024]    @ 163840 ( 16384)
//  sslot  u64[80*32]      @ 180224 ( 20480)
//  skey   u64[1024]       @ 200704 (  8192)
//  keepS  u32[1024]       @ 208896 (  4096)
//  scnt   u32[80]         @ 212992 (   320)
//  mbar   u64[8]          @ 213312 (    64)
static constexpr int SMEM_BYTES = 213376;

__device__ __forceinline__ unsigned smem_u32(const void* p) {
    return (unsigned)__cvta_generic_to_shared(p);
}

__device__ __forceinline__ void mbar_init(unsigned mb, unsigned cnt) {
    asm volatile("mbarrier.init.shared.b64 [%0], %1;" :: "r"(mb), "r"(cnt) : "memory");
}

__device__ __forceinline__ void issue_chunk(const float* src, unsigned dst, unsigned mb) {
    asm volatile("mbarrier.arrive.expect_tx.shared.b64 _, [%0], %1;"
                 :: "r"(mb), "r"((unsigned)CHUNK_BYTES) : "memory");
    asm volatile("cp.async.bulk.shared::cluster.global.mbarrier::complete_tx::bytes "
                 "[%0], [%1], %2, [%3];"
                 :: "r"(dst), "l"(src), "r"((unsigned)CHUNK_BYTES), "r"(mb) : "memory");
}

__device__ __forceinline__ void wait_parity(unsigned mb, unsigned ph) {
    asm volatile(
        "{\n\t.reg .pred P1;\n\t"
        "WAITL_%=:\n\t"
        "mbarrier.try_wait.parity.acquire.cta.shared::cta.b64 P1, [%0], %1, 0x989680;\n\t"
        "@P1 bra.uni WDONE_%=;\n\t"
        "bra.uni WAITL_%=;\n\t"
        "WDONE_%=:\n\t}"
        :: "r"(mb), "r"(ph) : "memory");
}

__device__ __forceinline__ unsigned long long bitonic_shfl_step(
    unsigned long long key, int j, bool up, int t)
{
    unsigned long long p = __shfl_xor_sync(FULL, key, j);
    bool low     = ((t & j) == 0);
    bool takeMin = (low == up);
    bool swap    = takeMin ? (p < key) : (p > key);
    return swap ? p : key;
}

__global__ __launch_bounds__(1024, 1)
void fastestdet_kernel(const float* __restrict__ in, float* __restrict__ out)
{
    extern __shared__ unsigned char smem_raw[];
    float*              ringf = (float*)(smem_raw);
    float4*             sbox  = (float4*)(smem_raw + 163840);
    unsigned long long* sslot = (unsigned long long*)(smem_raw + 180224);
    unsigned long long* skey  = (unsigned long long*)(smem_raw + 200704);
    unsigned*           keepS = (unsigned*)(smem_raw + 208896);
    unsigned*           scnt  = (unsigned*)(smem_raw + 212992);

    const unsigned ring_u32 = smem_u32(smem_raw);
    const unsigned mbar_u32 = ring_u32 + 213312;

    const int n    = blockIdx.x;
    const int t    = threadIdx.x;
    const int lane = t & 31;
    const int wid  = t >> 5;

    keepS[t] = 0u;
    if (t < NCLS) scnt[t] = 0u;

    const float* gbase = in + (size_t)n * NCH * HW;

    if (t == 0) {
        #pragma unroll
        for (int s = 0; s < RING; s++) mbar_init(mbar_u32 + s * 8, 1u);
        asm volatile("fence.proxy.async.shared::cta;" ::: "memory");
    }
    __syncthreads();

    if (t == 0) {
        #pragma unroll
        for (int k = 0; k < RING; k++)
            issue_chunk(gbase + (size_t)k * CHUNK_CH * HW,
                        ring_u32 + (unsigned)(k & 7) * CHUNK_BYTES,
                        mbar_u32 + (unsigned)(k & 7) * 8);
    }

    // ---------------- decode: TMA ring consume, per-pixel argmax ----------------
    float pobj = 0.f, r0 = 0.f, r1 = 0.f, r2 = 0.f, r3 = 0.f;
    float best = -INFINITY;
    int   bi   = 0;

    for (int k = 0; k < NCHUNK; k++) {
        const int s = k & 7;
        wait_parity(mbar_u32 + s * 8, (unsigned)((k >> 3) & 1));

        const float* cf = ringf + s * (CHUNK_CH * HW);
        if (k == 0) {
            pobj = cf[0 * HW + t];
            r0   = cf[1 * HW + t];
            r1   = cf[2 * HW + t];
            r2   = cf[3 * HW + t];
            r3   = cf[4 * HW + t];
        } else {
            const int c0 = (k - 1) * CHUNK_CH;      // class index of first channel
            #pragma unroll
            for (int j = 0; j < CHUNK_CH; j++) {
                float v = cf[j * HW + t];
                if (v > best) { best = v; bi = c0 + j; }   // ascending order: first occurrence
            }
        }
        __syncthreads();                             // slot free for reuse
        if (t == 0 && k + RING < NCHUNK)
            issue_chunk(gbase + (size_t)(k + RING) * CHUNK_CH * HW,
                        ring_u32 + (unsigned)s * CHUNK_BYTES,
                        mbar_u32 + (unsigned)s * 8);
    }

    // ---------------- box math + outputs + candidate scatter ----------------
    {
        float score = pobj * best;
        float gx = (float)(t & 31);
        float gy = (float)(t >> 5);
        float bcx = (tanhf(r0) + gx) * (1.0f / 32.0f);
        float bcy = (tanhf(r1) + gy) * (1.0f / 32.0f);
        float bw  = 1.0f / (1.0f + expf(-r2));
        float bh  = 1.0f / (1.0f + expf(-r3));
        float x1 = bcx - 0.5f * bw;
        float y1 = bcy - 0.5f * bh;
        float x2 = bcx + 0.5f * bw;
        float y2 = bcy + 0.5f * bh;

        float* ob = out + ((size_t)n * HW + t) * 6;
        ob[0] = x1; ob[1] = y1; ob[2] = x2; ob[3] = y2;
        ob[4] = score; ob[5] = (float)bi;

        sbox[t] = make_float4(x1, y1, x2, y2);

        bool cand = score > CONF_TH;
        unsigned u = __float_as_uint(score);
        u = (u & 0x80000000u) ? ~u : (u | 0x80000000u);   // ascending-sortable
        unsigned long long key = cand
            ? (((unsigned long long)(unsigned)bi << 42)
               | ((unsigned long long)(~u) << 10)
               | (unsigned)t)
            : (0x8000000000000000ull | (unsigned)t);
        skey[t] = key;
        if (cand) {
            unsigned slot = atomicAdd(&scnt[bi], 1u);
            if (slot < SLOTS) sslot[bi * SLOTS + slot] = key;
        }
    }
    __syncthreads();

    // ---------------- warp-per-class greedy NMS (smem, no barriers) ----------------
    for (int c = wid; c < NCLS; c += 32) {
        int m = (int)scnt[c];
        if (m == 0) continue;

        if (m <= SLOTS) {
            // fast path: sort ≤32 keys in registers, ballot-greedy
            unsigned long long kk = (lane < m) ? sslot[c * SLOTS + lane] : ~0ull;
            #pragma unroll
            for (int k = 2; k <= 32; k <<= 1) {
                #pragma unroll
                for (int j = k >> 1; j >= 1; j >>= 1)
                    kk = bitonic_shfl_step(kk, j, (lane & k) == 0, lane);
            }
            int pos = (int)(kk & 0x3FFu);
            float4 b4 = sbox[pos];                 // lane>=m: pos=1023, in-bounds, unused
            float  ar = (b4.z - b4.x) * (b4.w - b4.y);

            unsigned removed = 0u, keepB = 0u;
            for (int i = 0; i < m; i++) {
                if ((removed >> i) & 1u) continue; // uniform across warp
                keepB |= 1u << i;
                float wx1 = __shfl_sync(FULL, b4.x, i);
                float wy1 = __shfl_sync(FULL, b4.y, i);
                float wx2 = __shfl_sync(FULL, b4.z, i);
                float wy2 = __shfl_sync(FULL, b4.w, i);
                float wa  = __shfl_sync(FULL, ar,   i);
                float iw = fminf(b4.z, wx2) - fmaxf(b4.x, wx1);
                float ih = fminf(b4.w, wy2) - fmaxf(b4.y, wy1);
                iw = fmaxf(iw, 0.0f);
                ih = fmaxf(ih, 0.0f);
                float inter = iw * ih;
                bool s = (lane > i) && (lane < m) &&
                         (inter > NMS_TH * (ar + wa - inter + 1e-9f));
                removed |= __ballot_sync(FULL, s);
            }
            if (lane < m && ((keepB >> lane) & 1u)) keepS[pos] = 1u;
        } else {
            // generic fallback (astronomically rare): scan all pixel keys
            unsigned alive = 0u;            // lane owns pixels k*32+lane
            for (int k = 0; k < 32; k++) {
                unsigned long long key = skey[k * 32 + lane];
                bool elig = ((key >> 63) == 0ull) && ((int)((key >> 42) & 0x7Fu) == c);
                if (elig) alive |= 1u << k;
            }
            while (true) {
                unsigned long long bestk = ~0ull;
                for (int k = 0; k < 32; k++)
                    if ((alive >> k) & 1u) {
                        unsigned long long key = skey[k * 32 + lane];
                        if (key < bestk) bestk = key;
                    }
                #pragma unroll
                for (int d = 16; d >= 1; d >>= 1) {
                    unsigned long long o = __shfl_xor_sync(FULL, bestk, d);
                    if (o < bestk) bestk = o;
                }
                if (bestk == ~0ull) break;
                int wpos = (int)(bestk & 0x3FFu);
                float4 wb = sbox[wpos];
                float  wa = (wb.z - wb.x) * (wb.w - wb.y);
                if (lane == (wpos & 31)) {
                    alive &= ~(1u << (wpos >> 5));
                    keepS[wpos] = 1u;
                }
                for (int k = 0; k < 32; k++)
                    if ((alive >> k) & 1u) {
                        int p2 = k * 32 + lane;
                        float4 b2 = sbox[p2];
                        float a2 = (b2.z - b2.x) * (b2.w - b2.y);
                        float iw = fminf(b2.z, wb.z) - fmaxf(b2.x, wb.x);
                        float ih = fminf(b2.w, wb.w) - fmaxf(b2.y, wb.y);
                        iw = fmaxf(iw, 0.0f);
                        ih = fmaxf(ih, 0.0f);
                        float inter = iw * ih;
                        if (inter > NMS_TH * (a2 + wa - inter + 1e-9f))
                            alive &= ~(1u << k);
                    }
                __syncwarp(FULL);
            }
        }
    }
    __syncthreads();

    // ---------------- keep output (original order) ----------------
    out[(size_t)N_IMG * HW * 6 + (size_t)n * HW + t] = (float)keepS[t];
}

extern "C" void kernel_launch(void* const* d_in, const int* in_sizes, int n_in,
                              void* d_out, int out_size)
{
    const float* in = (const float*)d_in[0];
    float* out = (float*)d_out;
    cudaFuncSetAttribute(fastestdet_kernel,
                         cudaFuncAttributeMaxDynamicSharedMemorySize, SMEM_BYTES);
    fastestdet_kernel<<<N_IMG, 1024, SMEM_BYTES>>>(in, out);
}

// round 10
// speedup vs baseline: 1.3933x; 1.3933x over previous
#include <cuda_runtime.h>
#include <math.h>

#define CONF_TH 0.25f
#define NMS_TH  0.35f
#define FULL    0xffffffffu

static constexpr int N_IMG = 64;
static constexpr int HW    = 1024;   // 32*32
static constexpr int NCH   = 85;
static constexpr int NCLS  = 80;
static constexpr int SLOTS = 32;
static constexpr int NTASK = N_IMG * NCLS;

// static scratch (zero-initialized; zero-invariant restored every run)
__device__ float4             g_box  [N_IMG * HW];
__device__ unsigned long long g_key  [N_IMG * HW];
__device__ unsigned           g_cnt  [NTASK];
__device__ unsigned long long g_slots[NTASK * SLOTS];
__device__ unsigned           g_done [N_IMG];

// smem: pval float4[1024] (16K) + pidx int4[1024] (16K) + ticket flag
static constexpr int SMEM_BYTES = 32768 + 16;

__device__ __forceinline__ unsigned long long bitonic_shfl_step(
    unsigned long long key, int j, bool up, int t)
{
    unsigned long long p = __shfl_xor_sync(FULL, key, j);
    bool low     = ((t & j) == 0);
    bool takeMin = (low == up);
    bool swap    = takeMin ? (p < key) : (p > key);
    return swap ? p : key;
}

__global__ __launch_bounds__(1024, 1)
void fastestdet_kernel(const float* __restrict__ in, float* __restrict__ out)
{
    extern __shared__ unsigned char smem_raw[];
    float4*   pval  = (float4*)(smem_raw);
    int4*     pidx  = (int4*)  (smem_raw + 16384);
    unsigned* ticket = (unsigned*)(smem_raw + 32768);

    const int n    = blockIdx.x >> 1;   // image
    const int half = blockIdx.x & 1;    // half-image
    const int t    = threadIdx.x;
    const int lane = t & 31;
    const int wid  = t >> 5;
    const int g    = t & 127;    // pixel group (4 px) within half
    const int q    = t >> 7;     // class chunk (10 classes each, 8 chunks)

    // ---------------- decode phase 1: partial argmax over 10 classes ----------------
    const float4* base = (const float4*)(in + (size_t)n * NCH * HW) + half * 128 + g;
    // channel c lives at base[c*256]

    float4 bv = make_float4(-INFINITY, -INFINITY, -INFINITY, -INFINITY);
    int4   bj = make_int4(0, 0, 0, 0);
    const int c0 = q * 10;
    #pragma unroll
    for (int cc = 0; cc < 10; cc++) {
        int c = c0 + cc;
        float4 v = base[(5 + c) * 256];
        if (v.x > bv.x) { bv.x = v.x; bj.x = c; }
        if (v.y > bv.y) { bv.y = v.y; bj.y = c; }
        if (v.z > bv.z) { bv.z = v.z; bj.z = c; }
        if (v.w > bv.w) { bv.w = v.w; bj.w = c; }
    }
    pval[q * 128 + g] = bv;
    pidx[q * 128 + g] = bj;

    float4 pobj, r0, r1, r2, r3;
    if (q == 0) {
        pobj = base[0 * 256];
        r0   = base[1 * 256];
        r1   = base[2 * 256];
        r2   = base[3 * 256];
        r3   = base[4 * 256];
    }
    __syncthreads();

    // ---------------- decode phase 2: merge + box math (chunk-0 threads) ----------------
    if (q == 0) {
        float4 mv = pval[g];
        int4   mj = pidx[g];
        #pragma unroll
        for (int qq = 1; qq < 8; qq++) {
            float4 v = pval[qq * 128 + g];
            int4   j = pidx[qq * 128 + g];
            if (v.x > mv.x) { mv.x = v.x; mj.x = j.x; }   // strict >: lower class wins ties
            if (v.y > mv.y) { mv.y = v.y; mj.y = j.y; }
            if (v.z > mv.z) { mv.z = v.z; mj.z = j.z; }
            if (v.w > mv.w) { mv.w = v.w; mj.w = j.w; }
        }

        float sc[4]  = { pobj.x * mv.x, pobj.y * mv.y, pobj.z * mv.z, pobj.w * mv.w };
        float rr0[4] = { r0.x, r0.y, r0.z, r0.w };
        float rr1[4] = { r1.x, r1.y, r1.z, r1.w };
        float rr2[4] = { r2.x, r2.y, r2.z, r2.w };
        float rr3[4] = { r3.x, r3.y, r3.z, r3.w };
        int   cl[4]  = { mj.x, mj.y, mj.z, mj.w };

        float vals[24];
        #pragma unroll
        for (int l = 0; l < 4; l++) {
            int p = half * 512 + g * 4 + l;
            float gx = (float)(p & 31);
            float gy = (float)(p >> 5);
            float bcx = (tanhf(rr0[l]) + gx) * (1.0f / 32.0f);
            float bcy = (tanhf(rr1[l]) + gy) * (1.0f / 32.0f);
            float bw  = 1.0f / (1.0f + expf(-rr2[l]));
            float bh  = 1.0f / (1.0f + expf(-rr3[l]));
            float x1 = bcx - 0.5f * bw;
            float y1 = bcy - 0.5f * bh;
            float x2 = bcx + 0.5f * bw;
            float y2 = bcy + 0.5f * bh;

            vals[l * 6 + 0] = x1; vals[l * 6 + 1] = y1;
            vals[l * 6 + 2] = x2; vals[l * 6 + 3] = y2;
            vals[l * 6 + 4] = sc[l]; vals[l * 6 + 5] = (float)cl[l];

            g_box[(size_t)n * HW + p] = make_float4(x1, y1, x2, y2);

            bool cand = sc[l] > CONF_TH;
            unsigned u = __float_as_uint(sc[l]);
            u = (u & 0x80000000u) ? ~u : (u | 0x80000000u);   // ascending-sortable
            unsigned long long key = cand
                ? (((unsigned long long)(unsigned)cl[l] << 42)
                   | ((unsigned long long)(~u) << 10)
                   | (unsigned)p)
                : (0x8000000000000000ull | (unsigned)p);
            g_key[(size_t)n * HW + p] = key;
            if (cand) {
                int task = n * NCLS + cl[l];
                unsigned slot = atomicAdd(&g_cnt[task], 1u);
                if (slot < SLOTS) g_slots[task * SLOTS + slot] = key;
            }
        }

        // boxes+score+cls out: 24 contiguous floats = 6 float4 stores
        float4* ob4 = (float4*)(out + ((size_t)n * HW + half * 512 + g * 4) * 6);
        #pragma unroll
        for (int qq = 0; qq < 6; qq++)
            ob4[qq] = make_float4(vals[qq * 4 + 0], vals[qq * 4 + 1],
                                  vals[qq * 4 + 2], vals[qq * 4 + 3]);

        // keep region default zeros for this CTA's half
        *(float4*)(out + (size_t)N_IMG * HW * 6 + (size_t)n * HW + half * 512 + g * 4) =
            make_float4(0.0f, 0.0f, 0.0f, 0.0f);
    }

    // ---------------- ticket: last CTA of the image runs NMS ----------------
    __threadfence();
    __syncthreads();
    if (t == 0) *ticket = atomicAdd(&g_done[n], 1u);
    __syncthreads();
    if (*ticket != 1u) return;     // first CTA exits; second proceeds
    __threadfence();               // acquire side of the fence/ticket pattern

    float* keep = out + (size_t)N_IMG * HW * 6 + (size_t)n * HW;
    const float4* boxes = &g_box[(size_t)n * HW];

    // ---------------- warp-per-class greedy NMS (≤3 classes/warp) ----------------
    for (int c = wid; c < NCLS; c += 32) {
        const int task = n * NCLS + c;
        int m = (int)g_cnt[task];
        if (m == 0) continue;

        if (m <= SLOTS) {
            // fast path: sort ≤32 keys in registers, ballot-greedy
            unsigned long long kk = (lane < m) ? g_slots[task * SLOTS + lane] : ~0ull;
            #pragma unroll
            for (int k = 2; k <= 32; k <<= 1) {
                #pragma unroll
                for (int j = k >> 1; j >= 1; j >>= 1)
                    kk = bitonic_shfl_step(kk, j, (lane & k) == 0, lane);
            }
            int pos = (int)(kk & 0x3FFu);
            float4 b4 = boxes[pos];                // lane>=m: pos=1023, in-bounds, unused
            float  ar = (b4.z - b4.x) * (b4.w - b4.y);

            unsigned removed = 0u, keepB = 0u;
            for (int i = 0; i < m; i++) {
                if ((removed >> i) & 1u) continue; // uniform across warp
                keepB |= 1u << i;
                float wx1 = __shfl_sync(FULL, b4.x, i);
                float wy1 = __shfl_sync(FULL, b4.y, i);
                float wx2 = __shfl_sync(FULL, b4.z, i);
                float wy2 = __shfl_sync(FULL, b4.w, i);
                float wa  = __shfl_sync(FULL, ar,   i);
                float iw = fminf(b4.z, wx2) - fmaxf(b4.x, wx1);
                float ih = fminf(b4.w, wy2) - fmaxf(b4.y, wy1);
                iw = fmaxf(iw, 0.0f);
                ih = fmaxf(ih, 0.0f);
                float inter = iw * ih;
                bool s = (lane > i) && (lane < m) &&
                         (inter > NMS_TH * (ar + wa - inter + 1e-9f));
                removed |= __ballot_sync(FULL, s);
            }
            if (lane < m && ((keepB >> lane) & 1u)) keep[pos] = 1.0f;
        } else {
            // generic fallback (astronomically rare): scan all pixel keys of the image
            const unsigned long long* keys = &g_key[(size_t)n * HW];
            unsigned alive = 0u;            // lane owns pixels k*32+lane
            for (int k = 0; k < 32; k++) {
                unsigned long long key = keys[k * 32 + lane];
                bool elig = ((key >> 63) == 0ull) && ((int)((key >> 42) & 0x7Fu) == c);
                if (elig) alive |= 1u << k;
            }
            while (true) {
                unsigned long long bestk = ~0ull;
                for (int k = 0; k < 32; k++)
                    if ((alive >> k) & 1u) {
                        unsigned long long key = keys[k * 32 + lane];
                        if (key < bestk) bestk = key;
                    }
                #pragma unroll
                for (int d = 16; d >= 1; d >>= 1) {
                    unsigned long long o = __shfl_xor_sync(FULL, bestk, d);
                    if (o < bestk) bestk = o;
                }
                if (bestk == ~0ull) break;
                int wpos = (int)(bestk & 0x3FFu);
                float4 wb = boxes[wpos];
                float  wa = (wb.z - wb.x) * (wb.w - wb.y);
                if (lane == (wpos & 31)) {
                    alive &= ~(1u << (wpos >> 5));
                    keep[wpos] = 1.0f;
                }
                for (int k = 0; k < 32; k++)
                    if ((alive >> k) & 1u) {
                        int p2 = k * 32 + lane;
                        float4 b2 = boxes[p2];
                        float a2 = (b2.z - b2.x) * (b2.w - b2.y);
                        float iw = fminf(b2.z, wb.z) - fmaxf(b2.x, wb.x);
                        float ih = fminf(b2.w, wb.w) - fmaxf(b2.y, wb.y);
                        iw = fmaxf(iw, 0.0f);
                        ih = fmaxf(ih, 0.0f);
                        float inter = iw * ih;
                        if (inter > NMS_TH * (a2 + wa - inter + 1e-9f))
                            alive &= ~(1u << k);
                    }
                __syncwarp(FULL);
            }
        }
    }
    __syncthreads();

    // ---------------- restore zero-invariant for next graph replay ----------------
    if (t < NCLS) g_cnt[n * NCLS + t] = 0u;
    if (t == 0)   g_done[n] = 0u;
}

extern "C" void kernel_launch(void* const* d_in, const int* in_sizes, int n_in,
                              void* d_out, int out_size)
{
    const float* in = (const float*)d_in[0];
    float* out = (float*)d_out;
    cudaFuncSetAttribute(fastestdet_kernel,
                         cudaFuncAttributeMaxDynamicSharedMemorySize, SMEM_BYTES);
    fastestdet_kernel<<<N_IMG * 2, 1024, SMEM_BYTES>>>(in, out);
}

// round 12
// speedup vs baseline: 1.4439x; 1.0363x over previous
#include <cuda_runtime.h>
#include <math.h>

#define CONF_TH 0.25f
#define NMS_TH  0.35f
#define FULL    0xffffffffu

static constexpr int N_IMG = 64;
static constexpr int HW    = 1024;   // 32*32
static constexpr int NCH   = 85;
static constexpr int NCLS  = 80;
static constexpr int SLOTS = 32;

static constexpr int CHUNK_CH    = 5;                    // channels per chunk
static constexpr int CHUNK_FLT   = CHUNK_CH * HW;        // 5120 floats
static constexpr int CHUNK_BYTES = CHUNK_FLT * 4;        // 20480
static constexpr int NCHUNK      = NCH / CHUNK_CH;       // 17
static constexpr int RING        = 8;

// dynamic smem layout (bytes):
//  ring   float[8*5120]  @      0 (163840)
//  sbox   float4[1024]   @ 163840 ( 16384)
//  sslot  u64[80*32]     @ 180224 ( 20480)
//  skey   u64[1024]      @ 200704 (  8192)
//  keepS  u32[1024]      @ 208896 (  4096)
//  scnt   u32[80]        @ 212992 (   320)
static constexpr int SMEM_BYTES = 213312;

__device__ __forceinline__ void cp16(unsigned dst, const void* src) {
    asm volatile("cp.async.cg.shared.global [%0], [%1], 16;"
                 :: "r"(dst), "l"(src) : "memory");
}
__device__ __forceinline__ void cp_commit() {
    asm volatile("cp.async.commit_group;" ::: "memory");
}
__device__ __forceinline__ void cp_wait7() {
    asm volatile("cp.async.wait_group 7;" ::: "memory");
}

__device__ __forceinline__ unsigned long long bitonic_shfl_step(
    unsigned long long key, int j, bool up, int t)
{
    unsigned long long p = __shfl_xor_sync(FULL, key, j);
    bool low     = ((t & j) == 0);
    bool takeMin = (low == up);
    bool swap    = takeMin ? (p < key) : (p > key);
    return swap ? p : key;
}

__global__ __launch_bounds__(1024, 1)
void fastestdet_kernel(const float* __restrict__ in, float* __restrict__ out)
{
    extern __shared__ unsigned char smem_raw[];
    float*              ringf = (float*)(smem_raw);
    float4*             sbox  = (float4*)(smem_raw + 163840);
    unsigned long long* sslot = (unsigned long long*)(smem_raw + 180224);
    unsigned long long* skey  = (unsigned long long*)(smem_raw + 200704);
    unsigned*           keepS = (unsigned*)(smem_raw + 208896);
    unsigned*           scnt  = (unsigned*)(smem_raw + 212992);

    const unsigned ring_u32 = (unsigned)__cvta_generic_to_shared(smem_raw);

    const int n    = blockIdx.x;
    const int t    = threadIdx.x;
    const int lane = t & 31;
    const int wid  = t >> 5;

    keepS[t] = 0u;
    if (t < NCLS) scnt[t] = 0u;

    const char* gbase = (const char*)(in + (size_t)n * NCH * HW);

    // ---------------- prologue: fill the ring (8 chunks in flight) ----------------
    #pragma unroll
    for (int k = 0; k < RING; k++) {
        const char* src = gbase + (size_t)k * CHUNK_BYTES;
        unsigned dst = ring_u32 + (unsigned)k * CHUNK_BYTES;
        cp16(dst + t * 16, src + t * 16);
        if (t < 256) cp16(dst + (1024 + t) * 16, src + (1024 + t) * 16);
        cp_commit();
    }

    // ---------------- decode: pipelined consume + per-pixel argmax ----------------
    float pobj = 0.f, r0 = 0.f, r1 = 0.f, r2 = 0.f, r3 = 0.f;
    float best = -INFINITY;
    int   bi   = 0;

    for (int k = 0; k < NCHUNK; k++) {
        const int s = k & 7;
        cp_wait7();                // chunk k's group retired (uniform group count/thread)
        __syncthreads();           // publish all threads' async copies

        const float* cf = ringf + s * CHUNK_FLT;
        if (k == 0) {
            pobj = cf[0 * HW + t];
            r0   = cf[1 * HW + t];
            r1   = cf[2 * HW + t];
            r2   = cf[3 * HW + t];
            r3   = cf[4 * HW + t];
        } else {
            const int c0 = (k - 1) * CHUNK_CH;     // class of first channel in chunk
            #pragma unroll
            for (int j = 0; j < CHUNK_CH; j++) {
                float v = cf[j * HW + t];
                if (v > best) { best = v; bi = c0 + j; }   // ascending: first occurrence
            }
        }
        __syncthreads();           // all consumed before slot overwrite

        if (k + RING < NCHUNK) {
            const char* src = gbase + (size_t)(k + RING) * CHUNK_BYTES;
            unsigned dst = ring_u32 + (unsigned)s * CHUNK_BYTES;
            cp16(dst + t * 16, src + t * 16);
            if (t < 256) cp16(dst + (1024 + t) * 16, src + (1024 + t) * 16);
        }
        cp_commit();               // empty group when nothing issued: keeps count uniform
    }

    // ---------------- box math + outputs + candidate scatter ----------------
    {
        float score = pobj * best;
        float gx = (float)(t & 31);
        float gy = (float)(t >> 5);
        float bcx = (tanhf(r0) + gx) * (1.0f / 32.0f);
        float bcy = (tanhf(r1) + gy) * (1.0f / 32.0f);
        float bw  = 1.0f / (1.0f + expf(-r2));
        float bh  = 1.0f / (1.0f + expf(-r3));
        float x1 = bcx - 0.5f * bw;
        float y1 = bcy - 0.5f * bh;
        float x2 = bcx + 0.5f * bw;
        float y2 = bcy + 0.5f * bh;

        float* ob = out + ((size_t)n * HW + t) * 6;
        ob[0] = x1; ob[1] = y1; ob[2] = x2; ob[3] = y2;
        ob[4] = score; ob[5] = (float)bi;

        sbox[t] = make_float4(x1, y1, x2, y2);

        bool cand = score > CONF_TH;
        unsigned u = __float_as_uint(score);
        u = (u & 0x80000000u) ? ~u : (u | 0x80000000u);   // ascending-sortable
        unsigned long long key = cand
            ? (((unsigned long long)(unsigned)bi << 42)
               | ((unsigned long long)(~u) << 10)
               | (unsigned)t)
            : (0x8000000000000000ull | (unsigned)t);
        skey[t] = key;
        if (cand) {
            unsigned slot = atomicAdd(&scnt[bi], 1u);
            if (slot < SLOTS) sslot[bi * SLOTS + slot] = key;
        }
    }
    __syncthreads();

    // ---------------- warp-per-class greedy NMS (smem, no barriers) ----------------
    for (int c = wid; c < NCLS; c += 32) {
        int m = (int)scnt[c];
        if (m == 0) continue;

        if (m <= SLOTS) {
            // fast path: sort ≤32 keys in registers, ballot-greedy
            unsigned long long kk = (lane < m) ? sslot[c * SLOTS + lane] : ~0ull;
            #pragma unroll
            for (int k = 2; k <= 32; k <<= 1) {
                #pragma unroll
                for (int j = k >> 1; j >= 1; j >>= 1)
                    kk = bitonic_shfl_step(kk, j, (lane & k) == 0, lane);
            }
            int pos = (int)(kk & 0x3FFu);
            float4 b4 = sbox[pos];                 // lane>=m: pos=1023, in-bounds, unused
            float  ar = (b4.z - b4.x) * (b4.w - b4.y);

            unsigned removed = 0u, keepB = 0u;
            for (int i = 0; i < m; i++) {
                if ((removed >> i) & 1u) continue; // uniform across warp
                keepB |= 1u << i;
                float wx1 = __shfl_sync(FULL, b4.x, i);
                float wy1 = __shfl_sync(FULL, b4.y, i);
                float wx2 = __shfl_sync(FULL, b4.z, i);
                float wy2 = __shfl_sync(FULL, b4.w, i);
                float wa  = __shfl_sync(FULL, ar,   i);
                float iw = fminf(b4.z, wx2) - fmaxf(b4.x, wx1);
                float ih = fminf(b4.w, wy2) - fmaxf(b4.y, wy1);
                iw = fmaxf(iw, 0.0f);
                ih = fmaxf(ih, 0.0f);
                float inter = iw * ih;
                bool s = (lane > i) && (lane < m) &&
                         (inter > NMS_TH * (ar + wa - inter + 1e-9f));
                removed |= __ballot_sync(FULL, s);
            }
            if (lane < m && ((keepB >> lane) & 1u)) keepS[pos] = 1u;
        } else {
            // generic fallback (astronomically rare): scan all pixel keys
            unsigned alive = 0u;            // lane owns pixels k*32+lane
            for (int k = 0; k < 32; k++) {
                unsigned long long key = skey[k * 32 + lane];
                bool elig = ((key >> 63) == 0ull) && ((int)((key >> 42) & 0x7Fu) == c);
                if (elig) alive |= 1u << k;
            }
            while (true) {
                unsigned long long bestk = ~0ull;
                for (int k = 0; k < 32; k++)
                    if ((alive >> k) & 1u) {
                        unsigned long long key = skey[k * 32 + lane];
                        if (key < bestk) bestk = key;
                    }
                #pragma unroll
                for (int d = 16; d >= 1; d >>= 1) {
                    unsigned long long o = __shfl_xor_sync(FULL, bestk, d);
                    if (o < bestk) bestk = o;
                }
                if (bestk == ~0ull) break;
                int wpos = (int)(bestk & 0x3FFu);
                float4 wb = sbox[wpos];
                float  wa = (wb.z - wb.x) * (wb.w - wb.y);
                if (lane == (wpos & 31)) {
                    alive &= ~(1u << (wpos >> 5));
                    keepS[wpos] = 1u;
                }
                for (int k = 0; k < 32; k++)
                    if ((alive >> k) & 1u) {
                        int p2 = k * 32 + lane;
                        float4 b2 = sbox[p2];
                        float a2 = (b2.z - b2.x) * (b2.w - b2.y);
                        float iw = fminf(b2.z, wb.z) - fmaxf(b2.x, wb.x);
                        float ih = fminf(b2.w, wb.w) - fmaxf(b2.y, wb.y);
                        iw = fmaxf(iw, 0.0f);
                        ih = fmaxf(ih, 0.0f);
                        float inter = iw * ih;
                        if (inter > NMS_TH * (a2 + wa - inter + 1e-9f))
                            alive &= ~(1u << k);
                    }
                __syncwarp(FULL);
            }
        }
    }
    __syncthreads();

    // ---------------- keep output (original order) ----------------
    out[(size_t)N_IMG * HW * 6 + (size_t)n * HW + t] = (float)keepS[t];
}

extern "C" void kernel_launch(void* const* d_in, const int* in_sizes, int n_in,
                              void* d_out, int out_size)
{
    const float* in = (const float*)d_in[0];
    float* out = (float*)d_out;
    cudaFuncSetAttribute(fastestdet_kernel,
                         cudaFuncAttributeMaxDynamicSharedMemorySize, SMEM_BYTES);
    fastestdet_kernel<<<N_IMG, 1024, SMEM_BYTES>>>(in, out);
}